// round 15
// baseline (speedup 1.0000x reference)
#include <cuda_runtime.h>
#include <cuda_bf16.h>
#include <math.h>
#include <stdint.h>

// Problem constants
#define NB    16
#define CIN   512
#define HW    56
#define HW2   3136        // 56*56
#define NCOL  50176       // NB*HW2  (columns: n*3136 + w*56 + h)
#define O2    1024        // 2*OUT_PLANES
#define NGRP  8
#define NBLK_BG 7168      // 896*8
#define NTILE 392         // NCOL/128
#define EPSV  1e-5f

// ---------------- device scratch (static, allocation-free) ----------------
__device__ __nv_bfloat16 g_xh[(size_t)NCOL * CIN];   // x^T hi: [col][c]
__device__ __nv_bfloat16 g_xl[(size_t)NCOL * CIN];   // x^T lo
__device__ __nv_bfloat16 g_wh[O2 * CIN];             // W hi: [o][c]
__device__ __nv_bfloat16 g_wl[O2 * CIN];             // W lo
__device__ float g_qkv[(size_t)O2 * NCOL];    // [o][col]
__device__ float2 g_qpart[(size_t)O2 * NTILE];// per-(o, n-tile) partial (sum, sumsq)
__device__ float g_qkvA[O2], g_qkvB[O2];      // BN scale/shift for qkv
__device__ float g_qk[(size_t)NBLK_BG * HW2];
__device__ float g_qr[(size_t)NBLK_BG * HW2];
__device__ float g_kr[(size_t)NBLK_BG * HW2];
__device__ float g_bstat[6 * NGRP * 896];     // per-(b,g) partial sums/sumsq
__device__ double g_sred[48];                 // reduced sim stats
__device__ float g_simA[24];                  // 3 types x 8 groups
__device__ float g_simC[NGRP];
__device__ float g_ov[(size_t)NCOL * O2];     // [row=b*56+i][o]  o=g*128+c*2+s
__device__ float2 g_opart2[(size_t)O2 * 896]; // per-(o, b) partial (sum, sumsq)
__device__ float g_oA[O2], g_oB[O2];          // out BN scale/shift

// =================== PTX helpers (compute_103 baseline only) ===================
__device__ __forceinline__ uint32_t smem_u32(const void* p) {
    uint32_t a;
    asm("{ .reg .u64 t; cvta.to.shared.u64 t, %1; cvt.u32.u64 %0, t; }" : "=r"(a) : "l"(p));
    return a;
}
__device__ __forceinline__ void cp16(uint32_t sts, const void* g) {
    asm volatile("cp.async.cg.shared.global [%0], [%1], 16;" :: "r"(sts), "l"(g) : "memory");
}
#define CP_COMMIT() asm volatile("cp.async.commit_group;" ::: "memory")
template <int N> __device__ __forceinline__ void cp_wait() {
    asm volatile("cp.async.wait_group %0;" :: "n"(N) : "memory");
}
#define SW64(o) ((o) ^ (((o) >> 3) & 0x30))

__device__ __forceinline__ void ldsm4(uint32_t* r, uint32_t addr) {
    asm volatile("ldmatrix.sync.aligned.m8n8.x4.shared.b16 {%0,%1,%2,%3}, [%4];"
                 : "=r"(r[0]), "=r"(r[1]), "=r"(r[2]), "=r"(r[3]) : "r"(addr));
}
__device__ __forceinline__ void mma16816(float* d, const uint32_t* a, const uint32_t* b) {
    asm volatile(
        "mma.sync.aligned.m16n8k16.row.col.f32.bf16.bf16.f32 "
        "{%0,%1,%2,%3}, {%4,%5,%6,%7}, {%8,%9}, {%0,%1,%2,%3};"
        : "+f"(d[0]), "+f"(d[1]), "+f"(d[2]), "+f"(d[3])
        : "r"(a[0]), "r"(a[1]), "r"(a[2]), "r"(a[3]), "r"(b[0]), "r"(b[1]));
}

// ---------------- K0a: split W into bf16 hi/lo ----------------
__global__ void k_wsplit(const float* __restrict__ W) {
    int idx = (blockIdx.x * 256 + threadIdx.x) * 4;
    float4 v = *(const float4*)(W + idx);
    float a[4] = {v.x, v.y, v.z, v.w};
    __nv_bfloat16 hi[4], lo[4];
    #pragma unroll
    for (int i = 0; i < 4; i++) {
        hi[i] = __float2bfloat16(a[i]);
        lo[i] = __float2bfloat16(a[i] - __bfloat162float(hi[i]));
    }
    *(__nv_bfloat162*)&g_wh[idx]     = __nv_bfloat162(hi[0], hi[1]);
    *(__nv_bfloat162*)&g_wh[idx + 2] = __nv_bfloat162(hi[2], hi[3]);
    *(__nv_bfloat162*)&g_wl[idx]     = __nv_bfloat162(lo[0], lo[1]);
    *(__nv_bfloat162*)&g_wl[idx + 2] = __nv_bfloat162(lo[2], lo[3]);
}

// ---------------- K0b: transpose+split x (R11 coalesced version) ----------------
__global__ __launch_bounds__(256) void k_split_x(const float* __restrict__ x) {
    int cb = blockIdx.x, hb = blockIdx.y, n = blockIdx.z;
    int c0 = cb * 16, h0 = hb * 8;
    __shared__ float t[16][9][57];
    int tid = threadIdx.x;
    for (int idx = tid; idx < 16 * 8 * 56; idx += 256) {
        int c = idx / 448, r = idx - c * 448;
        int h = r / 56, w = r - h * 56;
        t[c][h][w] = x[((size_t)(n * 512 + c0 + c) * 56 + (h0 + h)) * 56 + w];
    }
    __syncthreads();
    for (int lin = tid; lin < 56 * 8 * 8; lin += 256) {
        int c2 = lin & 7, h = (lin >> 3) & 7, w = lin >> 6;
        int c = c2 * 2;
        float a0 = t[c][h][w], a1 = t[c + 1][h][w];
        __nv_bfloat16 h0b = __float2bfloat16(a0);
        __nv_bfloat16 h1b = __float2bfloat16(a1);
        __nv_bfloat16 l0b = __float2bfloat16(a0 - __bfloat162float(h0b));
        __nv_bfloat16 l1b = __float2bfloat16(a1 - __bfloat162float(h1b));
        size_t col = (size_t)n * HW2 + w * 56 + (h0 + h);
        *(__nv_bfloat162*)&g_xh[col * CIN + c0 + c] = __nv_bfloat162(h0b, h1b);
        *(__nv_bfloat162*)&g_xl[col * CIN + c0 + c] = __nv_bfloat162(l0b, l1b);
    }
}

// ---------------- dummy: shifts ncu's captured launch (4th) onto k_gemm_mma ----------------
__global__ void k_dummy() {}

// ---------------- K1: mma.sync split-bf16 GEMM, KC=32, 3 stages, 2 CTAs/SM ----------------
#define KC 32
#define MAT_B 8192                  // 128 rows * 32 bf16 * 2B (64B rows, SW64)
#define STG_B (4 * MAT_B)           // AH AL BH BL = 32 KB
#define GEMM_SMEM (3 * STG_B)       // 96 KB -> 2 CTAs/SM
#define NSTG 16                     // 512 / 32

__global__ __launch_bounds__(256, 2) void k_gemm_mma() {
    extern __shared__ char smem[];
    uint32_t sb = smem_u32(smem);
    const int tid = threadIdx.x;
    const int lane = tid & 31, wid = tid >> 5;
    const int mt = blockIdx.x;      // 0..7
    const int nt = blockIdx.y;      // 0..391

    const int ldrow = tid >> 1;
    const int ldhalf = tid & 1;
    const __nv_bfloat16* gAh = g_wh + (size_t)(mt * 128 + ldrow) * CIN + ldhalf * 16;
    const __nv_bfloat16* gAl = g_wl + (size_t)(mt * 128 + ldrow) * CIN + ldhalf * 16;
    const __nv_bfloat16* gBh = g_xh + (size_t)(nt * 128 + ldrow) * CIN + ldhalf * 16;
    const __nv_bfloat16* gBl = g_xl + (size_t)(nt * 128 + ldrow) * CIN + ldhalf * 16;

    auto load_stage = [&](int s) {
        uint32_t base = sb + (uint32_t)(s % 3) * STG_B;
        int koff = s * KC;
        #pragma unroll
        for (int i = 0; i < 2; i++) {
            uint32_t sw = SW64((uint32_t)(ldrow * 64 + ldhalf * 32 + i * 16));
            cp16(base + sw, (const char*)(gAh + koff) + i * 16);
            cp16(base + MAT_B + sw, (const char*)(gAl + koff) + i * 16);
            cp16(base + 2 * MAT_B + sw, (const char*)(gBh + koff) + i * 16);
            cp16(base + 3 * MAT_B + sw, (const char*)(gBl + koff) + i * 16);
        }
        CP_COMMIT();
    };

    const int m0w = (wid & 3) * 32;
    const int n0w = (wid >> 2) * 64;
    uint32_t aRow[2], aXor[2];
    const uint32_t aCol = (uint32_t)((lane >> 4) << 4);
    #pragma unroll
    for (int mf = 0; mf < 2; mf++) {
        int r = m0w + mf * 16 + (lane & 15);
        aRow[mf] = (uint32_t)(r * 64);
        aXor[mf] = (uint32_t)(((r >> 1) & 3) << 4);
    }
    uint32_t bRow[4], bXor[4];
    const uint32_t bCol = (uint32_t)(((lane >> 3) & 1) << 4);
    #pragma unroll
    for (int nb = 0; nb < 4; nb++) {
        int nrow = n0w + nb * 16 + ((lane >> 4) << 3) + (lane & 7);
        bRow[nb] = (uint32_t)(nrow * 64);
        bXor[nb] = (uint32_t)(((nrow >> 1) & 3) << 4);
    }

    float acc[2][8][4];
    #pragma unroll
    for (int mf = 0; mf < 2; mf++)
        #pragma unroll
        for (int nf = 0; nf < 8; nf++)
            #pragma unroll
            for (int u = 0; u < 4; u++) acc[mf][nf][u] = 0.f;

    load_stage(0);
    load_stage(1);

    for (int s = 0; s < NSTG; s++) {
        if (s < NSTG - 1) cp_wait<1>(); else cp_wait<0>();
        __syncthreads();
        if (s + 2 < NSTG) load_stage(s + 2);
        uint32_t base = sb + (uint32_t)(s % 3) * STG_B;
        #pragma unroll
        for (int k16 = 0; k16 < 2; k16++) {
            uint32_t kb = (uint32_t)(k16 * 32);
            uint32_t ah[2][4], al[2][4], bh[4][4], bl[4][4];
            #pragma unroll
            for (int mf = 0; mf < 2; mf++) {
                uint32_t off = aRow[mf] + ((aCol | kb) ^ aXor[mf]);
                ldsm4(ah[mf], base + off);
                ldsm4(al[mf], base + MAT_B + off);
            }
            #pragma unroll
            for (int nb = 0; nb < 4; nb++) {
                uint32_t off = bRow[nb] + ((bCol | kb) ^ bXor[nb]);
                ldsm4(bh[nb], base + 2 * MAT_B + off);
                ldsm4(bl[nb], base + 3 * MAT_B + off);
            }
            #pragma unroll
            for (int mf = 0; mf < 2; mf++)
                #pragma unroll
                for (int nb = 0; nb < 4; nb++)
                    #pragma unroll
                    for (int hf = 0; hf < 2; hf++) {
                        int nf = nb * 2 + hf;
                        mma16816(acc[mf][nf], ah[mf], &bh[nb][hf * 2]);
                        mma16816(acc[mf][nf], ah[mf], &bl[nb][hf * 2]);
                        mma16816(acc[mf][nf], al[mf], &bh[nb][hf * 2]);
                    }
        }
    }

    size_t colbase = (size_t)nt * 128;
    #pragma unroll
    for (int mf = 0; mf < 2; mf++) {
        int r0 = mt * 128 + m0w + mf * 16 + (lane >> 2);
        #pragma unroll
        for (int nf = 0; nf < 8; nf++) {
            int cb2 = n0w + nf * 8 + (lane & 3) * 2;
            float* d0 = g_qkv + (size_t)r0 * NCOL + colbase + cb2;
            float* d1 = g_qkv + (size_t)(r0 + 8) * NCOL + colbase + cb2;
            *(float2*)d0 = make_float2(acc[mf][nf][0], acc[mf][nf][1]);
            *(float2*)d1 = make_float2(acc[mf][nf][2], acc[mf][nf][3]);
        }
    }

    float prs[4] = {0, 0, 0, 0}, prq[4] = {0, 0, 0, 0};
    #pragma unroll
    for (int mf = 0; mf < 2; mf++)
        #pragma unroll
        for (int nf = 0; nf < 8; nf++) {
            prs[mf * 2 + 0] += acc[mf][nf][0] + acc[mf][nf][1];
            prq[mf * 2 + 0] += acc[mf][nf][0] * acc[mf][nf][0] + acc[mf][nf][1] * acc[mf][nf][1];
            prs[mf * 2 + 1] += acc[mf][nf][2] + acc[mf][nf][3];
            prq[mf * 2 + 1] += acc[mf][nf][2] * acc[mf][nf][2] + acc[mf][nf][3] * acc[mf][nf][3];
        }
    #pragma unroll
    for (int off = 1; off <= 2; off <<= 1)
        #pragma unroll
        for (int u = 0; u < 4; u++) {
            prs[u] += __shfl_xor_sync(0xffffffffu, prs[u], off);
            prq[u] += __shfl_xor_sync(0xffffffffu, prq[u], off);
        }
    __syncthreads();
    float2* sred = (float2*)smem;
    if ((lane & 3) == 0) {
        int q = lane >> 2;
        #pragma unroll
        for (int mf = 0; mf < 2; mf++)
            #pragma unroll
            for (int h = 0; h < 2; h++) {
                int rl = mf * 16 + h * 8 + q;
                sred[wid * 32 + rl] = make_float2(prs[mf * 2 + h], prq[mf * 2 + h]);
            }
    }
    __syncthreads();
    if (tid < 128) {
        int mg = tid >> 5, rl = tid & 31;
        float2 a2 = sred[mg * 32 + rl];
        float2 b2 = sred[(mg + 4) * 32 + rl];
        g_qpart[(size_t)(mt * 128 + mg * 32 + rl) * NTILE + nt] =
            make_float2(a2.x + b2.x, a2.y + b2.y);
    }
}

// ---------------- K2: reduce qkv partials -> BN coefficients ----------------
__global__ void k_qred(const float* __restrict__ gq, const float* __restrict__ bq) {
    int o = blockIdx.x;
    __shared__ double rs[128], rq2[128];
    double s = 0.0, q = 0.0;
    for (int p = threadIdx.x; p < NTILE; p += 128) {
        float2 v = g_qpart[(size_t)o * NTILE + p];
        s += (double)v.x; q += (double)v.y;
    }
    rs[threadIdx.x] = s; rq2[threadIdx.x] = q;
    __syncthreads();
    for (int st = 64; st > 0; st >>= 1) {
        if (threadIdx.x < st) { rs[threadIdx.x] += rs[threadIdx.x + st]; rq2[threadIdx.x] += rq2[threadIdx.x + st]; }
        __syncthreads();
    }
    if (threadIdx.x == 0) {
        double mean = rs[0] / (double)NCOL;
        double var  = rq2[0] / (double)NCOL - mean * mean;
        float a = gq[o] * (float)(1.0 / sqrt(var + 1e-5));
        g_qkvA[o] = a;
        g_qkvB[o] = bq[o] - (float)mean * a;
    }
}

// ---------------- K3: qk / qr / kr per (b,g) block, 4x4 register tiles ----------------
__global__ __launch_bounds__(224) void k_sim(const float* __restrict__ rel) {
    int blk = blockIdx.x;
    int b = blk >> 3, g = blk & 7;
    int n = b / 56, w = b - n * 56;
    long colbase = (long)n * HW2 + w * 56;

    __shared__ float q_s[32][60];
    __shared__ float k_s[32][60];
    __shared__ float rqs[32][112];
    __shared__ float rks[32][112];
    __shared__ float wred[7][6];

    int tid = threadIdx.x;
    for (int idx = tid; idx < 64 * 56; idx += 224) {
        int c = idx / 56, i = idx - c * 56;
        int o = g * 128 + c;
        float v = g_qkv[(long)o * NCOL + colbase + i] * g_qkvA[o] + g_qkvB[o];
        if (c < 32) q_s[c][i] = v; else k_s[c - 32][i] = v;
    }
    for (int idx = tid; idx < 64 * 111; idx += 224) {
        int c = idx / 111, t2 = idx - c * 111;
        float v = rel[c * 111 + t2];
        if (c < 32) rqs[c][t2] = v; else rks[c - 32][t2] = v;
    }
    if (tid < 64) { if (tid < 32) rqs[tid][111] = 0.f; else rks[tid - 32][111] = 0.f; }
    __syncthreads();

    float qk_a[4][4], qr_a[4][4], kr_a[4][4];
    #pragma unroll
    for (int a = 0; a < 4; a++)
        #pragma unroll
        for (int b2 = 0; b2 < 4; b2++) { qk_a[a][b2] = 0.f; qr_a[a][b2] = 0.f; kr_a[a][b2] = 0.f; }

    float s0 = 0, s1 = 0, s2 = 0, q0 = 0, q1 = 0, q2 = 0;

    if (tid < 196) {
        const int it = tid / 14, jt = tid % 14;
        const int i0 = it * 4, jj0 = jt * 4;
        const int dq = i0 - jj0 + 52;
        const int dk = jj0 - i0 + 52;

        #pragma unroll 4
        for (int c = 0; c < 32; c++) {
            const float4 qv = *(const float4*)&q_s[c][i0];
            const float4 kv = *(const float4*)&k_s[c][jj0];
            const float4 r0 = *(const float4*)&rqs[c][dq];
            const float4 r1 = *(const float4*)&rqs[c][dq + 4];
            const float4 t0 = *(const float4*)&rks[c][dk];
            const float4 t1 = *(const float4*)&rks[c][dk + 4];
            const float qa[4] = {qv.x, qv.y, qv.z, qv.w};
            const float kb[4] = {kv.x, kv.y, kv.z, kv.w};
            const float rqe[7] = {r0.x, r0.y, r0.z, r0.w, r1.x, r1.y, r1.z};
            const float rke[7] = {t0.x, t0.y, t0.z, t0.w, t1.x, t1.y, t1.z};
            #pragma unroll
            for (int a = 0; a < 4; a++)
                #pragma unroll
                for (int b2 = 0; b2 < 4; b2++) {
                    qk_a[a][b2] += qa[a] * kb[b2];
                    qr_a[a][b2] += qa[a] * rqe[a - b2 + 3];
                    kr_a[a][b2] += kb[b2] * rke[b2 - a + 3];
                }
        }

        float* oqk = g_qk + (long)blk * HW2;
        float* oqr = g_qr + (long)blk * HW2;
        float* okr = g_kr + (long)blk * HW2;
        #pragma unroll
        for (int a = 0; a < 4; a++) {
            int i = i0 + a;
            *(float4*)&oqk[i * 56 + jj0] = make_float4(qk_a[a][0], qk_a[a][1], qk_a[a][2], qk_a[a][3]);
            *(float4*)&oqr[i * 56 + jj0] = make_float4(qr_a[a][0], qr_a[a][1], qr_a[a][2], qr_a[a][3]);
            *(float4*)&okr[i * 56 + jj0] = make_float4(kr_a[a][0], kr_a[a][1], kr_a[a][2], kr_a[a][3]);
            #pragma unroll
            for (int b2 = 0; b2 < 4; b2++) {
                float v0 = qk_a[a][b2], v1 = qr_a[a][b2], v2 = kr_a[a][b2];
                s0 += v0; q0 += v0 * v0;
                s1 += v1; q1 += v1 * v1;
                s2 += v2; q2 += v2 * v2;
            }
        }
    }

    #pragma unroll
    for (int off = 16; off > 0; off >>= 1) {
        s0 += __shfl_down_sync(0xffffffffu, s0, off);
        s1 += __shfl_down_sync(0xffffffffu, s1, off);
        s2 += __shfl_down_sync(0xffffffffu, s2, off);
        q0 += __shfl_down_sync(0xffffffffu, q0, off);
        q1 += __shfl_down_sync(0xffffffffu, q1, off);
        q2 += __shfl_down_sync(0xffffffffu, q2, off);
    }
    int lane = tid & 31, warp = tid >> 5;
    if (lane == 0) {
        wred[warp][0] = s0; wred[warp][1] = s1; wred[warp][2] = s2;
        wred[warp][3] = q0; wred[warp][4] = q1; wred[warp][5] = q2;
    }
    __syncthreads();
    if (tid == 0) {
        float t[6] = {0, 0, 0, 0, 0, 0};
        for (int wv = 0; wv < 7; wv++)
            for (int u = 0; u < 6; u++) t[u] += wred[wv][u];
        for (int u = 0; u < 6; u++)
            g_bstat[(u * NGRP + g) * 896 + b] = t[u];
    }
}

// ---------------- K4: reduce sim stat partials ----------------
__global__ void k_simred() {
    int qg = blockIdx.x;                   // 0..47
    __shared__ double rd[128];
    double acc = 0.0;
    for (int b = threadIdx.x; b < 896; b += 128)
        acc += (double)g_bstat[qg * 896 + b];
    rd[threadIdx.x] = acc;
    __syncthreads();
    for (int st = 64; st > 0; st >>= 1) {
        if (threadIdx.x < st) rd[threadIdx.x] += rd[threadIdx.x + st];
        __syncthreads();
    }
    if (threadIdx.x == 0) g_sred[qg] = rd[0];
}

// ---------------- K5: sim BN coefficients ----------------
__global__ void k_simcoef(const float* __restrict__ gs, const float* __restrict__ bs) {
    int g = threadIdx.x;
    if (g >= NGRP) return;
    const double ntot = 896.0 * 3136.0;
    float cc = 0.f;
    for (int t = 0; t < 3; t++) {
        double S = g_sred[t * 8 + g];
        double Q = g_sred[(t + 3) * 8 + g];
        double mean = S / ntot;
        double var  = Q / ntot - mean * mean;
        float a = gs[t * 8 + g] * (float)(1.0 / sqrt(var + 1e-5));
        g_simA[t * 8 + g] = a;
        cc += bs[t * 8 + g] - (float)mean * a;
    }
    g_simC[g] = cc;
}

// ---------------- K6: softmax + sv/sve per (b,g) + fused out-BN partials ----------------
// Phase B batched by 4 j: float4 v (v_s padded to 60), broadcast float4 p,
// 7-entry scalar Toeplitz window with static indices. Mapping/reduction as R8.
__global__ __launch_bounds__(128) void k_attn(const float* __restrict__ rel) {
    int blk = blockIdx.x;
    int b = blk >> 3, g = blk & 7;
    int n = b / 56, w = b - n * 56;
    long colbase = (long)n * HW2 + w * 56;

    __shared__ float v_s[64][60];      // padded: rows 16B-aligned for float4
    __shared__ float rv[64][111];
    __shared__ float p_s[4][56];       // 224B rows -> float4-aligned
    __shared__ float red[2][64][8];

    int tid = threadIdx.x;
    for (int idx = tid; idx < 64 * 56; idx += 128) {
        int c = idx / 56, i = idx - c * 56;
        int o = g * 128 + 64 + c;
        v_s[c][i] = g_qkv[(long)o * NCOL + colbase + i] * g_qkvA[o] + g_qkvB[o];
    }
    for (int idx = tid; idx < 64 * 111; idx += 128) {
        int c = idx / 111, t2 = idx - c * 111;
        rv[c][t2] = rel[(64 + c) * 111 + t2];
    }
    float a0 = g_simA[g], a1 = g_simA[8 + g], a2 = g_simA[16 + g], cc = g_simC[g];
    const float* bqk = g_qk + (long)blk * HW2;
    const float* bqr = g_qr + (long)blk * HW2;
    const float* bkr = g_kr + (long)blk * HW2;
    __syncthreads();

    int lane = tid & 31, warp = tid >> 5;
    int c = tid & 63, jh = tid >> 6;       // jh 0..1
    const int jbeg = jh * 28;

    float ssv = 0.f, qsv = 0.f, sse = 0.f, qse = 0.f;

    for (int iq = 0; iq < 14; iq++) {
        int i0 = iq * 4;
        {
            int i = i0 + warp;
            int j1 = lane, j2 = lane + 32;
            const float* pk = bqk + i * 56;
            const float* pr = bqr + i * 56;
            const float* pl = bkr + i * 56;
            float sA = a0 * pk[j1] + a1 * pr[j1] + a2 * pl[j1] + cc;
            float sB = (j2 < 56) ? (a0 * pk[j2] + a1 * pr[j2] + a2 * pl[j2] + cc) : -1e30f;
            float m = fmaxf(sA, sB);
            #pragma unroll
            for (int off = 16; off > 0; off >>= 1)
                m = fmaxf(m, __shfl_xor_sync(0xffffffffu, m, off));
            float e1 = __expf(sA - m);
            float e2 = (j2 < 56) ? __expf(sB - m) : 0.f;
            float sm = e1 + e2;
            #pragma unroll
            for (int off = 16; off > 0; off >>= 1)
                sm += __shfl_xor_sync(0xffffffffu, sm, off);
            float inv = 1.f / sm;
            p_s[warp][j1] = e1 * inv;
            if (j2 < 56) p_s[warp][j2] = e2 * inv;
        }
        __syncthreads();

        // ---- phase B: 28 j's in 7 groups of 4 ----
        float sv[4] = {0, 0, 0, 0}, se[4] = {0, 0, 0, 0};
        // wnd[k] = rv[c][i0 - j0 + 52 + k] for current group base j0
        float wnd[7];
        #pragma unroll
        for (int k = 0; k < 7; k++) wnd[k] = rv[c][i0 - jbeg + 52 + k];

        for (int jg = 0; jg < 7; jg++) {
            int j0 = jbeg + jg * 4;
            const float4 vv = *(const float4*)&v_s[c][j0];
            const float4 p0 = *(const float4*)&p_s[0][j0];
            const float4 p1 = *(const float4*)&p_s[1][j0];
            const float4 p2 = *(const float4*)&p_s[2][j0];
            const float4 p3 = *(const float4*)&p_s[3][j0];
            const float va[4] = {vv.x, vv.y, vv.z, vv.w};
            const float pd[4][4] = {{p0.x, p0.y, p0.z, p0.w},
                                    {p1.x, p1.y, p1.z, p1.w},
                                    {p2.x, p2.y, p2.z, p2.w},
                                    {p3.x, p3.y, p3.z, p3.w}};
            #pragma unroll
            for (int jj = 0; jj < 4; jj++)
                #pragma unroll
                for (int d = 0; d < 4; d++) {
                    sv[d] += pd[d][jj] * va[jj];
                    se[d] += pd[d][jj] * wnd[3 + d - jj];   // static index
                }
            if (jg < 6) {
                wnd[6] = wnd[2]; wnd[5] = wnd[1]; wnd[4] = wnd[0];
                #pragma unroll
                for (int k = 0; k < 4; k++)
                    wnd[k] = rv[c][i0 - jbeg + 48 - jg * 4 + k];
            }
        }

        #pragma unroll
        for (int d = 0; d < 4; d++) { red[jh][c][d] = sv[d]; red[jh][c][4 + d] = se[d]; }
        __syncthreads();
        if (jh == 0) {
            #pragma unroll
            for (int d = 0; d < 4; d++) {
                float svt = red[0][c][d] + red[1][c][d];
                float set = red[0][c][4 + d] + red[1][c][4 + d];
                long row = (long)b * 56 + (i0 + d);
                ((float2*)(g_ov + row * O2 + g * 128))[c] = make_float2(svt, set);
                ssv += svt; qsv += svt * svt;
                sse += set; qse += set * set;
            }
        }
        // no third barrier: next iteration's post-softmax barrier provides ordering.
    }

    if (jh == 0) {
        int o0 = g * 128 + 2 * c;
        g_opart2[(size_t)o0 * 896 + b]       = make_float2(ssv, qsv);
        g_opart2[(size_t)(o0 + 1) * 896 + b] = make_float2(sse, qse);
    }
}

// ---------------- K7: reduce out-BN partials -> coefficients ----------------
__global__ void k_ofin2(const float* __restrict__ go, const float* __restrict__ bo) {
    int o = blockIdx.x;
    __shared__ double rs[128], rq2[128];
    double s = 0.0, q = 0.0;
    for (int p = threadIdx.x; p < 896; p += 128) {
        float2 v = g_opart2[(size_t)o * 896 + p];
        s += (double)v.x; q += (double)v.y;
    }
    rs[threadIdx.x] = s; rq2[threadIdx.x] = q;
    __syncthreads();
    for (int st = 64; st > 0; st >>= 1) {
        if (threadIdx.x < st) { rs[threadIdx.x] += rs[threadIdx.x + st]; rq2[threadIdx.x] += rq2[threadIdx.x + st]; }
        __syncthreads();
    }
    if (threadIdx.x == 0) {
        double mean = rs[0] / (double)NCOL;
        double var  = rq2[0] / (double)NCOL - mean * mean;
        float a = go[o] * (float)(1.0 / sqrt(var + 1e-5));
        g_oA[o] = a;
        g_oB[o] = bo[o] - (float)mean * a;
    }
}

// ---------------- K8: final BN + pair-sum + transpose ----------------
__global__ __launch_bounds__(256) void k_out(float* __restrict__ out) {
    int pt = blockIdx.x, h = blockIdx.y, n = blockIdx.z;
    int p0 = pt * 64;
    __shared__ float tile[56][65];
    int tid = threadIdx.x;
    for (int lin = tid; lin < 56 * 64; lin += 256) {
        int w = lin >> 6, pl = lin & 63;
        int p = p0 + pl;
        long row = (long)n * HW2 + w * 56 + h;
        float2 v = *(const float2*)&g_ov[row * O2 + p * 2];
        tile[w][pl] = g_oA[2 * p] * v.x + g_oA[2 * p + 1] * v.y + g_oB[2 * p] + g_oB[2 * p + 1];
    }
    __syncthreads();
    for (int lin = tid; lin < 56 * 64; lin += 256) {
        int pl = lin / 56, w2 = lin - pl * 56;
        out[(((long)n * 512 + p0 + pl) * 56 + h) * 56 + w2] = tile[w2][pl];
    }
}

// ---------------- launch ----------------
extern "C" void kernel_launch(void* const* d_in, const int* in_sizes, int n_in,
                              void* d_out, int out_size) {
    const float* x     = (const float*)d_in[0];
    const float* w_qkv = (const float*)d_in[1];
    const float* rel   = (const float*)d_in[2];
    const float* g_q   = (const float*)d_in[3];
    const float* b_q   = (const float*)d_in[4];
    const float* g_s   = (const float*)d_in[5];
    const float* b_s   = (const float*)d_in[6];
    const float* g_o   = (const float*)d_in[7];
    const float* b_o   = (const float*)d_in[8];
    float* out = (float*)d_out;

    cudaFuncSetAttribute(k_gemm_mma, cudaFuncAttributeMaxDynamicSharedMemorySize, GEMM_SMEM);

    k_wsplit<<<O2 * CIN / 1024, 256>>>(w_qkv);       // launch 1
    k_split_x<<<dim3(32, 7, NB), 256>>>(x);          // launch 2
    k_dummy<<<1, 32>>>();                            // launch 3
    k_gemm_mma<<<dim3(8, NTILE), 256, GEMM_SMEM>>>();// launch 4 <- profiled
    k_qred<<<O2, 128>>>(g_q, b_q);
    k_sim<<<NBLK_BG, 224>>>(rel);
    k_simred<<<48, 128>>>();
    k_simcoef<<<1, 32>>>(g_s, b_s);
    k_attn<<<NBLK_BG, 128>>>(rel);
    k_ofin2<<<O2, 128>>>(g_o, b_o);
    k_out<<<dim3(8, 56, NB), 256>>>(out);
}

// round 16
// speedup vs baseline: 1.0114x; 1.0114x over previous
#include <cuda_runtime.h>
#include <cuda_bf16.h>
#include <math.h>
#include <stdint.h>

// Problem constants
#define NB    16
#define CIN   512
#define HW    56
#define HW2   3136        // 56*56
#define NCOL  50176       // NB*HW2  (columns: n*3136 + w*56 + h)
#define O2    1024        // 2*OUT_PLANES
#define NGRP  8
#define NBLK_BG 7168      // 896*8
#define NTILE 392         // NCOL/128
#define EPSV  1e-5f

// ---------------- device scratch (static, allocation-free) ----------------
__device__ __nv_bfloat16 g_xh[(size_t)NCOL * CIN];   // x^T hi: [col][c]
__device__ __nv_bfloat16 g_xl[(size_t)NCOL * CIN];   // x^T lo
__device__ __nv_bfloat16 g_wh[O2 * CIN];             // W hi: [o][c]
__device__ __nv_bfloat16 g_wl[O2 * CIN];             // W lo
__device__ float g_qkv[(size_t)O2 * NCOL];    // [o][col]
__device__ float2 g_qpart[(size_t)O2 * NTILE];// per-(o, n-tile) partial (sum, sumsq)
__device__ float g_qkvA[O2], g_qkvB[O2];      // BN scale/shift for qkv
__device__ float g_qk[(size_t)NBLK_BG * HW2];
__device__ float g_qr[(size_t)NBLK_BG * HW2];
__device__ float g_kr[(size_t)NBLK_BG * HW2];
__device__ float g_bstat[6 * NGRP * 896];     // per-(b,g) partial sums/sumsq
__device__ double g_sred[48];                 // reduced sim stats
__device__ float g_simA[24];                  // 3 types x 8 groups
__device__ float g_simC[NGRP];
__device__ float g_ov[(size_t)NCOL * O2];     // [row=b*56+i][o]  o=g*128+c*2+s
__device__ float2 g_opart2[(size_t)O2 * 896]; // per-(o, b) partial (sum, sumsq)
__device__ float g_oA[O2], g_oB[O2];          // out BN scale/shift

// =================== PTX helpers (compute_103 baseline only) ===================
__device__ __forceinline__ uint32_t smem_u32(const void* p) {
    uint32_t a;
    asm("{ .reg .u64 t; cvta.to.shared.u64 t, %1; cvt.u32.u64 %0, t; }" : "=r"(a) : "l"(p));
    return a;
}
__device__ __forceinline__ void cp16(uint32_t sts, const void* g) {
    asm volatile("cp.async.cg.shared.global [%0], [%1], 16;" :: "r"(sts), "l"(g) : "memory");
}
#define CP_COMMIT() asm volatile("cp.async.commit_group;" ::: "memory")
template <int N> __device__ __forceinline__ void cp_wait() {
    asm volatile("cp.async.wait_group %0;" :: "n"(N) : "memory");
}
#define SW64(o) ((o) ^ (((o) >> 3) & 0x30))

__device__ __forceinline__ void ldsm4(uint32_t* r, uint32_t addr) {
    asm volatile("ldmatrix.sync.aligned.m8n8.x4.shared.b16 {%0,%1,%2,%3}, [%4];"
                 : "=r"(r[0]), "=r"(r[1]), "=r"(r[2]), "=r"(r[3]) : "r"(addr));
}
__device__ __forceinline__ void mma16816(float* d, const uint32_t* a, const uint32_t* b) {
    asm volatile(
        "mma.sync.aligned.m16n8k16.row.col.f32.bf16.bf16.f32 "
        "{%0,%1,%2,%3}, {%4,%5,%6,%7}, {%8,%9}, {%0,%1,%2,%3};"
        : "+f"(d[0]), "+f"(d[1]), "+f"(d[2]), "+f"(d[3])
        : "r"(a[0]), "r"(a[1]), "r"(a[2]), "r"(a[3]), "r"(b[0]), "r"(b[1]));
}

// ---------------- K0a: split W into bf16 hi/lo ----------------
__global__ void k_wsplit(const float* __restrict__ W) {
    int idx = (blockIdx.x * 256 + threadIdx.x) * 4;
    float4 v = *(const float4*)(W + idx);
    float a[4] = {v.x, v.y, v.z, v.w};
    __nv_bfloat16 hi[4], lo[4];
    #pragma unroll
    for (int i = 0; i < 4; i++) {
        hi[i] = __float2bfloat16(a[i]);
        lo[i] = __float2bfloat16(a[i] - __bfloat162float(hi[i]));
    }
    *(__nv_bfloat162*)&g_wh[idx]     = __nv_bfloat162(hi[0], hi[1]);
    *(__nv_bfloat162*)&g_wh[idx + 2] = __nv_bfloat162(hi[2], hi[3]);
    *(__nv_bfloat162*)&g_wl[idx]     = __nv_bfloat162(lo[0], lo[1]);
    *(__nv_bfloat162*)&g_wl[idx + 2] = __nv_bfloat162(lo[2], lo[3]);
}

// ---------------- K0b: transpose+split x (coalesced 32B-sector writes) ----------------
__global__ __launch_bounds__(256) void k_split_x(const float* __restrict__ x) {
    int cb = blockIdx.x, hb = blockIdx.y, n = blockIdx.z;
    int c0 = cb * 16, h0 = hb * 8;
    __shared__ float t[16][9][57];
    int tid = threadIdx.x;
    for (int idx = tid; idx < 16 * 8 * 56; idx += 256) {
        int c = idx / 448, r = idx - c * 448;
        int h = r / 56, w = r - h * 56;
        t[c][h][w] = x[((size_t)(n * 512 + c0 + c) * 56 + (h0 + h)) * 56 + w];
    }
    __syncthreads();
    for (int lin = tid; lin < 56 * 8 * 8; lin += 256) {
        int c2 = lin & 7, h = (lin >> 3) & 7, w = lin >> 6;
        int c = c2 * 2;
        float a0 = t[c][h][w], a1 = t[c + 1][h][w];
        __nv_bfloat16 h0b = __float2bfloat16(a0);
        __nv_bfloat16 h1b = __float2bfloat16(a1);
        __nv_bfloat16 l0b = __float2bfloat16(a0 - __bfloat162float(h0b));
        __nv_bfloat16 l1b = __float2bfloat16(a1 - __bfloat162float(h1b));
        size_t col = (size_t)n * HW2 + w * 56 + (h0 + h);
        *(__nv_bfloat162*)&g_xh[col * CIN + c0 + c] = __nv_bfloat162(h0b, h1b);
        *(__nv_bfloat162*)&g_xl[col * CIN + c0 + c] = __nv_bfloat162(l0b, l1b);
    }
}

// ---------------- K1: mma.sync split-bf16 GEMM, KC=32, 3 stages, 2 CTAs/SM ----------------
#define KC 32
#define MAT_B 8192                  // 128 rows * 32 bf16 * 2B (64B rows, SW64)
#define STG_B (4 * MAT_B)           // AH AL BH BL = 32 KB
#define GEMM_SMEM (3 * STG_B)       // 96 KB -> 2 CTAs/SM
#define NSTG 16                     // 512 / 32

__global__ __launch_bounds__(256, 2) void k_gemm_mma() {
    extern __shared__ char smem[];
    uint32_t sb = smem_u32(smem);
    const int tid = threadIdx.x;
    const int lane = tid & 31, wid = tid >> 5;
    const int mt = blockIdx.x;      // 0..7  (fastest -> B reuse in L2)
    const int nt = blockIdx.y;      // 0..391

    const int ldrow = tid >> 1;
    const int ldhalf = tid & 1;
    const __nv_bfloat16* gAh = g_wh + (size_t)(mt * 128 + ldrow) * CIN + ldhalf * 16;
    const __nv_bfloat16* gAl = g_wl + (size_t)(mt * 128 + ldrow) * CIN + ldhalf * 16;
    const __nv_bfloat16* gBh = g_xh + (size_t)(nt * 128 + ldrow) * CIN + ldhalf * 16;
    const __nv_bfloat16* gBl = g_xl + (size_t)(nt * 128 + ldrow) * CIN + ldhalf * 16;

    auto load_stage = [&](int s) {
        uint32_t base = sb + (uint32_t)(s % 3) * STG_B;
        int koff = s * KC;
        #pragma unroll
        for (int i = 0; i < 2; i++) {
            uint32_t sw = SW64((uint32_t)(ldrow * 64 + ldhalf * 32 + i * 16));
            cp16(base + sw, (const char*)(gAh + koff) + i * 16);
            cp16(base + MAT_B + sw, (const char*)(gAl + koff) + i * 16);
            cp16(base + 2 * MAT_B + sw, (const char*)(gBh + koff) + i * 16);
            cp16(base + 3 * MAT_B + sw, (const char*)(gBl + koff) + i * 16);
        }
        CP_COMMIT();
    };

    const int m0w = (wid & 3) * 32;
    const int n0w = (wid >> 2) * 64;
    uint32_t aRow[2], aXor[2];
    const uint32_t aCol = (uint32_t)((lane >> 4) << 4);
    #pragma unroll
    for (int mf = 0; mf < 2; mf++) {
        int r = m0w + mf * 16 + (lane & 15);
        aRow[mf] = (uint32_t)(r * 64);
        aXor[mf] = (uint32_t)(((r >> 1) & 3) << 4);
    }
    uint32_t bRow[4], bXor[4];
    const uint32_t bCol = (uint32_t)(((lane >> 3) & 1) << 4);
    #pragma unroll
    for (int nb = 0; nb < 4; nb++) {
        int nrow = n0w + nb * 16 + ((lane >> 4) << 3) + (lane & 7);
        bRow[nb] = (uint32_t)(nrow * 64);
        bXor[nb] = (uint32_t)(((nrow >> 1) & 3) << 4);
    }

    float acc[2][8][4];
    #pragma unroll
    for (int mf = 0; mf < 2; mf++)
        #pragma unroll
        for (int nf = 0; nf < 8; nf++)
            #pragma unroll
            for (int u = 0; u < 4; u++) acc[mf][nf][u] = 0.f;

    load_stage(0);
    load_stage(1);

    for (int s = 0; s < NSTG; s++) {
        if (s < NSTG - 1) cp_wait<1>(); else cp_wait<0>();
        __syncthreads();
        if (s + 2 < NSTG) load_stage(s + 2);   // overlaps this stage's compute
        uint32_t base = sb + (uint32_t)(s % 3) * STG_B;
        #pragma unroll
        for (int k16 = 0; k16 < 2; k16++) {
            uint32_t kb = (uint32_t)(k16 * 32);
            uint32_t ah[2][4], al[2][4], bh[4][4], bl[4][4];
            #pragma unroll
            for (int mf = 0; mf < 2; mf++) {
                uint32_t off = aRow[mf] + ((aCol | kb) ^ aXor[mf]);
                ldsm4(ah[mf], base + off);
                ldsm4(al[mf], base + MAT_B + off);
            }
            #pragma unroll
            for (int nb = 0; nb < 4; nb++) {
                uint32_t off = bRow[nb] + ((bCol | kb) ^ bXor[nb]);
                ldsm4(bh[nb], base + 2 * MAT_B + off);
                ldsm4(bl[nb], base + 3 * MAT_B + off);
            }
            #pragma unroll
            for (int mf = 0; mf < 2; mf++)
                #pragma unroll
                for (int nb = 0; nb < 4; nb++)
                    #pragma unroll
                    for (int hf = 0; hf < 2; hf++) {
                        int nf = nb * 2 + hf;
                        mma16816(acc[mf][nf], ah[mf], &bh[nb][hf * 2]);
                        mma16816(acc[mf][nf], ah[mf], &bl[nb][hf * 2]);
                        mma16816(acc[mf][nf], al[mf], &bh[nb][hf * 2]);
                    }
        }
        // 3-stage ring: no trailing barrier needed
    }

    // ---- epilogue: write f32 results
    size_t colbase = (size_t)nt * 128;
    #pragma unroll
    for (int mf = 0; mf < 2; mf++) {
        int r0 = mt * 128 + m0w + mf * 16 + (lane >> 2);
        #pragma unroll
        for (int nf = 0; nf < 8; nf++) {
            int cb2 = n0w + nf * 8 + (lane & 3) * 2;
            float* d0 = g_qkv + (size_t)r0 * NCOL + colbase + cb2;
            float* d1 = g_qkv + (size_t)(r0 + 8) * NCOL + colbase + cb2;
            *(float2*)d0 = make_float2(acc[mf][nf][0], acc[mf][nf][1]);
            *(float2*)d1 = make_float2(acc[mf][nf][2], acc[mf][nf][3]);
        }
    }

    // ---- fused per-row partial BN stats over this CTA's 128 cols
    float prs[4] = {0, 0, 0, 0}, prq[4] = {0, 0, 0, 0};
    #pragma unroll
    for (int mf = 0; mf < 2; mf++)
        #pragma unroll
        for (int nf = 0; nf < 8; nf++) {
            prs[mf * 2 + 0] += acc[mf][nf][0] + acc[mf][nf][1];
            prq[mf * 2 + 0] += acc[mf][nf][0] * acc[mf][nf][0] + acc[mf][nf][1] * acc[mf][nf][1];
            prs[mf * 2 + 1] += acc[mf][nf][2] + acc[mf][nf][3];
            prq[mf * 2 + 1] += acc[mf][nf][2] * acc[mf][nf][2] + acc[mf][nf][3] * acc[mf][nf][3];
        }
    #pragma unroll
    for (int off = 1; off <= 2; off <<= 1)
        #pragma unroll
        for (int u = 0; u < 4; u++) {
            prs[u] += __shfl_xor_sync(0xffffffffu, prs[u], off);
            prq[u] += __shfl_xor_sync(0xffffffffu, prq[u], off);
        }
    __syncthreads();
    float2* sred = (float2*)smem;       // [8 warps][32 rows]
    if ((lane & 3) == 0) {
        int q = lane >> 2;
        #pragma unroll
        for (int mf = 0; mf < 2; mf++)
            #pragma unroll
            for (int h = 0; h < 2; h++) {
                int rl = mf * 16 + h * 8 + q;
                sred[wid * 32 + rl] = make_float2(prs[mf * 2 + h], prq[mf * 2 + h]);
            }
    }
    __syncthreads();
    if (tid < 128) {
        int mg = tid >> 5, rl = tid & 31;
        float2 a2 = sred[mg * 32 + rl];
        float2 b2 = sred[(mg + 4) * 32 + rl];
        g_qpart[(size_t)(mt * 128 + mg * 32 + rl) * NTILE + nt] =
            make_float2(a2.x + b2.x, a2.y + b2.y);
    }
}

// ---------------- K2: reduce qkv partials -> BN coefficients ----------------
__global__ void k_qred(const float* __restrict__ gq, const float* __restrict__ bq) {
    int o = blockIdx.x;
    __shared__ double rs[128], rq2[128];
    double s = 0.0, q = 0.0;
    for (int p = threadIdx.x; p < NTILE; p += 128) {
        float2 v = g_qpart[(size_t)o * NTILE + p];
        s += (double)v.x; q += (double)v.y;
    }
    rs[threadIdx.x] = s; rq2[threadIdx.x] = q;
    __syncthreads();
    for (int st = 64; st > 0; st >>= 1) {
        if (threadIdx.x < st) { rs[threadIdx.x] += rs[threadIdx.x + st]; rq2[threadIdx.x] += rq2[threadIdx.x + st]; }
        __syncthreads();
    }
    if (threadIdx.x == 0) {
        double mean = rs[0] / (double)NCOL;
        double var  = rq2[0] / (double)NCOL - mean * mean;
        float a = gq[o] * (float)(1.0 / sqrt(var + 1e-5));
        g_qkvA[o] = a;
        g_qkvB[o] = bq[o] - (float)mean * a;
    }
}

// ---------------- K3: qk / qr / kr per (b,g) block, 4x4 register tiles ----------------
__global__ __launch_bounds__(224) void k_sim(const float* __restrict__ rel) {
    int blk = blockIdx.x;
    int b = blk >> 3, g = blk & 7;
    int n = b / 56, w = b - n * 56;
    long colbase = (long)n * HW2 + w * 56;

    __shared__ float q_s[32][60];
    __shared__ float k_s[32][60];
    __shared__ float rqs[32][112];
    __shared__ float rks[32][112];
    __shared__ float wred[7][6];

    int tid = threadIdx.x;
    for (int idx = tid; idx < 64 * 56; idx += 224) {
        int c = idx / 56, i = idx - c * 56;
        int o = g * 128 + c;
        float v = g_qkv[(long)o * NCOL + colbase + i] * g_qkvA[o] + g_qkvB[o];
        if (c < 32) q_s[c][i] = v; else k_s[c - 32][i] = v;
    }
    for (int idx = tid; idx < 64 * 111; idx += 224) {
        int c = idx / 111, t2 = idx - c * 111;
        float v = rel[c * 111 + t2];
        if (c < 32) rqs[c][t2] = v; else rks[c - 32][t2] = v;
    }
    if (tid < 64) { if (tid < 32) rqs[tid][111] = 0.f; else rks[tid - 32][111] = 0.f; }
    __syncthreads();

    float qk_a[4][4], qr_a[4][4], kr_a[4][4];
    #pragma unroll
    for (int a = 0; a < 4; a++)
        #pragma unroll
        for (int b2 = 0; b2 < 4; b2++) { qk_a[a][b2] = 0.f; qr_a[a][b2] = 0.f; kr_a[a][b2] = 0.f; }

    float s0 = 0, s1 = 0, s2 = 0, q0 = 0, q1 = 0, q2 = 0;

    if (tid < 196) {
        const int it = tid / 14, jt = tid % 14;
        const int i0 = it * 4, jj0 = jt * 4;
        const int dq = i0 - jj0 + 52;
        const int dk = jj0 - i0 + 52;

        #pragma unroll 4
        for (int c = 0; c < 32; c++) {
            const float4 qv = *(const float4*)&q_s[c][i0];
            const float4 kv = *(const float4*)&k_s[c][jj0];
            const float4 r0 = *(const float4*)&rqs[c][dq];
            const float4 r1 = *(const float4*)&rqs[c][dq + 4];
            const float4 t0 = *(const float4*)&rks[c][dk];
            const float4 t1 = *(const float4*)&rks[c][dk + 4];
            const float qa[4] = {qv.x, qv.y, qv.z, qv.w};
            const float kb[4] = {kv.x, kv.y, kv.z, kv.w};
            const float rqe[7] = {r0.x, r0.y, r0.z, r0.w, r1.x, r1.y, r1.z};
            const float rke[7] = {t0.x, t0.y, t0.z, t0.w, t1.x, t1.y, t1.z};
            #pragma unroll
            for (int a = 0; a < 4; a++)
                #pragma unroll
                for (int b2 = 0; b2 < 4; b2++) {
                    qk_a[a][b2] += qa[a] * kb[b2];
                    qr_a[a][b2] += qa[a] * rqe[a - b2 + 3];
                    kr_a[a][b2] += kb[b2] * rke[b2 - a + 3];
                }
        }

        float* oqk = g_qk + (long)blk * HW2;
        float* oqr = g_qr + (long)blk * HW2;
        float* okr = g_kr + (long)blk * HW2;
        #pragma unroll
        for (int a = 0; a < 4; a++) {
            int i = i0 + a;
            *(float4*)&oqk[i * 56 + jj0] = make_float4(qk_a[a][0], qk_a[a][1], qk_a[a][2], qk_a[a][3]);
            *(float4*)&oqr[i * 56 + jj0] = make_float4(qr_a[a][0], qr_a[a][1], qr_a[a][2], qr_a[a][3]);
            *(float4*)&okr[i * 56 + jj0] = make_float4(kr_a[a][0], kr_a[a][1], kr_a[a][2], kr_a[a][3]);
            #pragma unroll
            for (int b2 = 0; b2 < 4; b2++) {
                float v0 = qk_a[a][b2], v1 = qr_a[a][b2], v2 = kr_a[a][b2];
                s0 += v0; q0 += v0 * v0;
                s1 += v1; q1 += v1 * v1;
                s2 += v2; q2 += v2 * v2;
            }
        }
    }

    #pragma unroll
    for (int off = 16; off > 0; off >>= 1) {
        s0 += __shfl_down_sync(0xffffffffu, s0, off);
        s1 += __shfl_down_sync(0xffffffffu, s1, off);
        s2 += __shfl_down_sync(0xffffffffu, s2, off);
        q0 += __shfl_down_sync(0xffffffffu, q0, off);
        q1 += __shfl_down_sync(0xffffffffu, q1, off);
        q2 += __shfl_down_sync(0xffffffffu, q2, off);
    }
    int lane = tid & 31, warp = tid >> 5;
    if (lane == 0) {
        wred[warp][0] = s0; wred[warp][1] = s1; wred[warp][2] = s2;
        wred[warp][3] = q0; wred[warp][4] = q1; wred[warp][5] = q2;
    }
    __syncthreads();
    if (tid == 0) {
        float t[6] = {0, 0, 0, 0, 0, 0};
        for (int wv = 0; wv < 7; wv++)
            for (int u = 0; u < 6; u++) t[u] += wred[wv][u];
        for (int u = 0; u < 6; u++)
            g_bstat[(u * NGRP + g) * 896 + b] = t[u];
    }
}

// ---------------- K4: reduce sim stat partials ----------------
__global__ void k_simred() {
    int qg = blockIdx.x;                   // 0..47
    __shared__ double rd[128];
    double acc = 0.0;
    for (int b = threadIdx.x; b < 896; b += 128)
        acc += (double)g_bstat[qg * 896 + b];
    rd[threadIdx.x] = acc;
    __syncthreads();
    for (int st = 64; st > 0; st >>= 1) {
        if (threadIdx.x < st) rd[threadIdx.x] += rd[threadIdx.x + st];
        __syncthreads();
    }
    if (threadIdx.x == 0) g_sred[qg] = rd[0];
}

// ---------------- K5: sim BN coefficients ----------------
__global__ void k_simcoef(const float* __restrict__ gs, const float* __restrict__ bs) {
    int g = threadIdx.x;
    if (g >= NGRP) return;
    const double ntot = 896.0 * 3136.0;
    float cc = 0.f;
    for (int t = 0; t < 3; t++) {
        double S = g_sred[t * 8 + g];
        double Q = g_sred[(t + 3) * 8 + g];
        double mean = S / ntot;
        double var  = Q / ntot - mean * mean;
        float a = gs[t * 8 + g] * (float)(1.0 / sqrt(var + 1e-5));
        g_simA[t * 8 + g] = a;
        cc += bs[t * 8 + g] - (float)mean * a;
    }
    g_simC[g] = cc;
}

// ---------------- K6: softmax + sv/sve per (b,g) + fused out-BN partials ----------------
__global__ __launch_bounds__(128) void k_attn(const float* __restrict__ rel) {
    int blk = blockIdx.x;
    int b = blk >> 3, g = blk & 7;
    int n = b / 56, w = b - n * 56;
    long colbase = (long)n * HW2 + w * 56;

    __shared__ float v_s[64][57];
    __shared__ float rv[64][111];
    __shared__ float p_s[4][56];
    __shared__ float red[2][64][8];

    int tid = threadIdx.x;
    for (int idx = tid; idx < 64 * 56; idx += 128) {
        int c = idx / 56, i = idx - c * 56;
        int o = g * 128 + 64 + c;
        v_s[c][i] = g_qkv[(long)o * NCOL + colbase + i] * g_qkvA[o] + g_qkvB[o];
    }
    for (int idx = tid; idx < 64 * 111; idx += 128) {
        int c = idx / 111, t2 = idx - c * 111;
        rv[c][t2] = rel[(64 + c) * 111 + t2];
    }
    float a0 = g_simA[g], a1 = g_simA[8 + g], a2 = g_simA[16 + g], cc = g_simC[g];
    const float* bqk = g_qk + (long)blk * HW2;
    const float* bqr = g_qr + (long)blk * HW2;
    const float* bkr = g_kr + (long)blk * HW2;
    __syncthreads();

    int lane = tid & 31, warp = tid >> 5;
    int c = tid & 63, jh = tid >> 6;       // jh 0..1

    float ssv = 0.f, qsv = 0.f, sse = 0.f, qse = 0.f;   // fused out-BN partials

    for (int iq = 0; iq < 14; iq++) {
        int i0 = iq * 4;
        {
            int i = i0 + warp;
            int j1 = lane, j2 = lane + 32;
            const float* pk = bqk + i * 56;
            const float* pr = bqr + i * 56;
            const float* pl = bkr + i * 56;
            float sA = a0 * pk[j1] + a1 * pr[j1] + a2 * pl[j1] + cc;
            float sB = (j2 < 56) ? (a0 * pk[j2] + a1 * pr[j2] + a2 * pl[j2] + cc) : -1e30f;
            float m = fmaxf(sA, sB);
            #pragma unroll
            for (int off = 16; off > 0; off >>= 1)
                m = fmaxf(m, __shfl_xor_sync(0xffffffffu, m, off));
            float e1 = __expf(sA - m);
            float e2 = (j2 < 56) ? __expf(sB - m) : 0.f;
            float sm = e1 + e2;
            #pragma unroll
            for (int off = 16; off > 0; off >>= 1)
                sm += __shfl_xor_sync(0xffffffffu, sm, off);
            float inv = 1.f / sm;
            p_s[warp][j1] = e1 * inv;
            if (j2 < 56) p_s[warp][j2] = e2 * inv;
        }
        __syncthreads();
        float sv[4] = {0, 0, 0, 0}, se[4] = {0, 0, 0, 0};
        int jbeg = jh * 28;
        float win[4];
        #pragma unroll
        for (int d = 0; d < 4; d++) win[d] = rv[c][i0 + d - jbeg + 55];
        for (int jo = 0; jo < 28; jo++) {
            int j = jbeg + jo;
            float vv = v_s[c][j];
            #pragma unroll
            for (int d = 0; d < 4; d++) {
                float p = p_s[d][j];
                sv[d] += p * vv;
                se[d] += p * win[d];
            }
            if (jo < 27) {
                #pragma unroll
                for (int d = 3; d > 0; d--) win[d] = win[d - 1];
                win[0] = rv[c][i0 - j + 54];
            }
        }
        #pragma unroll
        for (int d = 0; d < 4; d++) { red[jh][c][d] = sv[d]; red[jh][c][4 + d] = se[d]; }
        __syncthreads();
        if (jh == 0) {
            #pragma unroll
            for (int d = 0; d < 4; d++) {
                float svt = red[0][c][d] + red[1][c][d];
                float set = red[0][c][4 + d] + red[1][c][4 + d];
                long row = (long)b * 56 + (i0 + d);
                ((float2*)(g_ov + row * O2 + g * 128))[c] = make_float2(svt, set);
                ssv += svt; qsv += svt * svt;
                sse += set; qse += set * set;
            }
        }
        // no third barrier: next iteration's post-softmax barrier provides ordering.
    }

    if (jh == 0) {
        int o0 = g * 128 + 2 * c;
        g_opart2[(size_t)o0 * 896 + b]       = make_float2(ssv, qsv);
        g_opart2[(size_t)(o0 + 1) * 896 + b] = make_float2(sse, qse);
    }
}

// ---------------- K7: reduce out-BN partials -> coefficients ----------------
__global__ void k_ofin2(const float* __restrict__ go, const float* __restrict__ bo) {
    int o = blockIdx.x;
    __shared__ double rs[128], rq2[128];
    double s = 0.0, q = 0.0;
    for (int p = threadIdx.x; p < 896; p += 128) {
        float2 v = g_opart2[(size_t)o * 896 + p];
        s += (double)v.x; q += (double)v.y;
    }
    rs[threadIdx.x] = s; rq2[threadIdx.x] = q;
    __syncthreads();
    for (int st = 64; st > 0; st >>= 1) {
        if (threadIdx.x < st) { rs[threadIdx.x] += rs[threadIdx.x + st]; rq2[threadIdx.x] += rq2[threadIdx.x + st]; }
        __syncthreads();
    }
    if (threadIdx.x == 0) {
        double mean = rs[0] / (double)NCOL;
        double var  = rq2[0] / (double)NCOL - mean * mean;
        float a = go[o] * (float)(1.0 / sqrt(var + 1e-5));
        g_oA[o] = a;
        g_oB[o] = bo[o] - (float)mean * a;
    }
}

// ---------------- K8: final BN + pair-sum + transpose ----------------
__global__ __launch_bounds__(256) void k_out(float* __restrict__ out) {
    int pt = blockIdx.x, h = blockIdx.y, n = blockIdx.z;
    int p0 = pt * 64;
    __shared__ float tile[56][65];
    int tid = threadIdx.x;
    for (int lin = tid; lin < 56 * 64; lin += 256) {
        int w = lin >> 6, pl = lin & 63;
        int p = p0 + pl;
        long row = (long)n * HW2 + w * 56 + h;
        float2 v = *(const float2*)&g_ov[row * O2 + p * 2];
        tile[w][pl] = g_oA[2 * p] * v.x + g_oA[2 * p + 1] * v.y + g_oB[2 * p] + g_oB[2 * p + 1];
    }
    __syncthreads();
    for (int lin = tid; lin < 56 * 64; lin += 256) {
        int pl = lin / 56, w2 = lin - pl * 56;
        out[(((long)n * 512 + p0 + pl) * 56 + h) * 56 + w2] = tile[w2][pl];
    }
}

// ---------------- launch ----------------
extern "C" void kernel_launch(void* const* d_in, const int* in_sizes, int n_in,
                              void* d_out, int out_size) {
    const float* x     = (const float*)d_in[0];
    const float* w_qkv = (const float*)d_in[1];
    const float* rel   = (const float*)d_in[2];
    const float* g_q   = (const float*)d_in[3];
    const float* b_q   = (const float*)d_in[4];
    const float* g_s   = (const float*)d_in[5];
    const float* b_s   = (const float*)d_in[6];
    const float* g_o   = (const float*)d_in[7];
    const float* b_o   = (const float*)d_in[8];
    float* out = (float*)d_out;

    cudaFuncSetAttribute(k_gemm_mma, cudaFuncAttributeMaxDynamicSharedMemorySize, GEMM_SMEM);

    k_wsplit<<<O2 * CIN / 1024, 256>>>(w_qkv);
    k_split_x<<<dim3(32, 7, NB), 256>>>(x);
    k_gemm_mma<<<dim3(8, NTILE), 256, GEMM_SMEM>>>();
    k_qred<<<O2, 128>>>(g_q, b_q);
    k_sim<<<NBLK_BG, 224>>>(rel);
    k_simred<<<48, 128>>>();
    k_simcoef<<<1, 32>>>(g_s, b_s);
    k_attn<<<NBLK_BG, 128>>>(rel);
    k_ofin2<<<O2, 128>>>(g_o, b_o);
    k_out<<<dim3(8, 56, NB), 256>>>(out);
}

// round 17
// speedup vs baseline: 1.0680x; 1.0559x over previous
#include <cuda_runtime.h>
#include <cuda_bf16.h>
#include <math.h>
#include <stdint.h>

// Problem constants
#define NB    16
#define CIN   512
#define HW    56
#define HW2   3136        // 56*56
#define NCOL  50176       // NB*HW2  (columns: n*3136 + w*56 + h)
#define O2    1024        // 2*OUT_PLANES
#define NGRP  8
#define NBLK_BG 7168      // 896*8
#define NTILE 392         // NCOL/128
#define EPSV  1e-5f

// ---------------- device scratch (static, allocation-free) ----------------
__device__ __nv_bfloat16 g_xh[(size_t)NCOL * CIN];   // x^T hi: [col][c]
__device__ __nv_bfloat16 g_xl[(size_t)NCOL * CIN];   // x^T lo
__device__ __nv_bfloat16 g_wh[O2 * CIN];             // W hi: [o][c]
__device__ __nv_bfloat16 g_wl[O2 * CIN];             // W lo
__device__ float g_qkv[(size_t)O2 * NCOL];    // [o][col]
__device__ float2 g_qpart[(size_t)O2 * NTILE];// per-(o, n-tile) partial (sum, sumsq)
__device__ float g_qkvA[O2], g_qkvB[O2];      // BN scale/shift for qkv
__device__ float g_qk[(size_t)NBLK_BG * HW2];
__device__ float g_qr[(size_t)NBLK_BG * HW2];
__device__ float g_kr[(size_t)NBLK_BG * HW2];
__device__ float g_bstat[6 * NGRP * 896];     // per-(b,g) partial sums/sumsq
__device__ double g_sred[48];                 // reduced sim stats
__device__ float g_simA[24];                  // 3 types x 8 groups
__device__ float g_simC[NGRP];
__device__ float g_ov[(size_t)NCOL * O2];     // [row=b*56+i][o]  o=g*128+c*2+s
__device__ float2 g_opart2[(size_t)O2 * 896]; // per-(o, b) partial (sum, sumsq)
__device__ float g_oA[O2], g_oB[O2];          // out BN scale/shift

// =================== PTX helpers (compute_103 baseline only) ===================
__device__ __forceinline__ uint32_t smem_u32(const void* p) {
    uint32_t a;
    asm("{ .reg .u64 t; cvta.to.shared.u64 t, %1; cvt.u32.u64 %0, t; }" : "=r"(a) : "l"(p));
    return a;
}
__device__ __forceinline__ void cp16(uint32_t sts, const void* g) {
    asm volatile("cp.async.cg.shared.global [%0], [%1], 16;" :: "r"(sts), "l"(g) : "memory");
}
#define CP_COMMIT() asm volatile("cp.async.commit_group;" ::: "memory")
template <int N> __device__ __forceinline__ void cp_wait() {
    asm volatile("cp.async.wait_group %0;" :: "n"(N) : "memory");
}
#define SW64(o) ((o) ^ (((o) >> 3) & 0x30))

__device__ __forceinline__ void ldsm4(uint32_t* r, uint32_t addr) {
    asm volatile("ldmatrix.sync.aligned.m8n8.x4.shared.b16 {%0,%1,%2,%3}, [%4];"
                 : "=r"(r[0]), "=r"(r[1]), "=r"(r[2]), "=r"(r[3]) : "r"(addr));
}
__device__ __forceinline__ void mma16816(float* d, const uint32_t* a, const uint32_t* b) {
    asm volatile(
        "mma.sync.aligned.m16n8k16.row.col.f32.bf16.bf16.f32 "
        "{%0,%1,%2,%3}, {%4,%5,%6,%7}, {%8,%9}, {%0,%1,%2,%3};"
        : "+f"(d[0]), "+f"(d[1]), "+f"(d[2]), "+f"(d[3])
        : "r"(a[0]), "r"(a[1]), "r"(a[2]), "r"(a[3]), "r"(b[0]), "r"(b[1]));
}

// ---------------- K0a: split W into bf16 hi/lo ----------------
__global__ void k_wsplit(const float* __restrict__ W) {
    int idx = (blockIdx.x * 256 + threadIdx.x) * 4;
    float4 v = *(const float4*)(W + idx);
    float a[4] = {v.x, v.y, v.z, v.w};
    __nv_bfloat16 hi[4], lo[4];
    #pragma unroll
    for (int i = 0; i < 4; i++) {
        hi[i] = __float2bfloat16(a[i]);
        lo[i] = __float2bfloat16(a[i] - __bfloat162float(hi[i]));
    }
    *(__nv_bfloat162*)&g_wh[idx]     = __nv_bfloat162(hi[0], hi[1]);
    *(__nv_bfloat162*)&g_wh[idx + 2] = __nv_bfloat162(hi[2], hi[3]);
    *(__nv_bfloat162*)&g_wl[idx]     = __nv_bfloat162(lo[0], lo[1]);
    *(__nv_bfloat162*)&g_wl[idx + 2] = __nv_bfloat162(lo[2], lo[3]);
}

// ---------------- K0b: transpose+split x (coalesced 32B-sector writes) ----------------
__global__ __launch_bounds__(256) void k_split_x(const float* __restrict__ x) {
    int cb = blockIdx.x, hb = blockIdx.y, n = blockIdx.z;
    int c0 = cb * 16, h0 = hb * 8;
    __shared__ float t[16][9][57];
    int tid = threadIdx.x;
    for (int idx = tid; idx < 16 * 8 * 56; idx += 256) {
        int c = idx / 448, r = idx - c * 448;
        int h = r / 56, w = r - h * 56;
        t[c][h][w] = x[((size_t)(n * 512 + c0 + c) * 56 + (h0 + h)) * 56 + w];
    }
    __syncthreads();
    for (int lin = tid; lin < 56 * 8 * 8; lin += 256) {
        int c2 = lin & 7, h = (lin >> 3) & 7, w = lin >> 6;
        int c = c2 * 2;
        float a0 = t[c][h][w], a1 = t[c + 1][h][w];
        __nv_bfloat16 h0b = __float2bfloat16(a0);
        __nv_bfloat16 h1b = __float2bfloat16(a1);
        __nv_bfloat16 l0b = __float2bfloat16(a0 - __bfloat162float(h0b));
        __nv_bfloat16 l1b = __float2bfloat16(a1 - __bfloat162float(h1b));
        size_t col = (size_t)n * HW2 + w * 56 + (h0 + h);
        *(__nv_bfloat162*)&g_xh[col * CIN + c0 + c] = __nv_bfloat162(h0b, h1b);
        *(__nv_bfloat162*)&g_xl[col * CIN + c0 + c] = __nv_bfloat162(l0b, l1b);
    }
}

// ---------------- K1: mma.sync split-bf16 GEMM, KC=32, 3 stages, 2 CTAs/SM ----------------
#define KC 32
#define MAT_B 8192                  // 128 rows * 32 bf16 * 2B (64B rows, SW64)
#define STG_B (4 * MAT_B)           // AH AL BH BL = 32 KB
#define GEMM_SMEM (3 * STG_B)       // 96 KB -> 2 CTAs/SM
#define NSTG 16                     // 512 / 32

__global__ __launch_bounds__(256, 2) void k_gemm_mma() {
    extern __shared__ char smem[];
    uint32_t sb = smem_u32(smem);
    const int tid = threadIdx.x;
    const int lane = tid & 31, wid = tid >> 5;
    const int mt = blockIdx.x;      // 0..7  (fastest -> B reuse in L2)
    const int nt = blockIdx.y;      // 0..391

    const int ldrow = tid >> 1;
    const int ldhalf = tid & 1;
    const __nv_bfloat16* gAh = g_wh + (size_t)(mt * 128 + ldrow) * CIN + ldhalf * 16;
    const __nv_bfloat16* gAl = g_wl + (size_t)(mt * 128 + ldrow) * CIN + ldhalf * 16;
    const __nv_bfloat16* gBh = g_xh + (size_t)(nt * 128 + ldrow) * CIN + ldhalf * 16;
    const __nv_bfloat16* gBl = g_xl + (size_t)(nt * 128 + ldrow) * CIN + ldhalf * 16;

    auto load_stage = [&](int s) {
        uint32_t base = sb + (uint32_t)(s % 3) * STG_B;
        int koff = s * KC;
        #pragma unroll
        for (int i = 0; i < 2; i++) {
            uint32_t sw = SW64((uint32_t)(ldrow * 64 + ldhalf * 32 + i * 16));
            cp16(base + sw, (const char*)(gAh + koff) + i * 16);
            cp16(base + MAT_B + sw, (const char*)(gAl + koff) + i * 16);
            cp16(base + 2 * MAT_B + sw, (const char*)(gBh + koff) + i * 16);
            cp16(base + 3 * MAT_B + sw, (const char*)(gBl + koff) + i * 16);
        }
        CP_COMMIT();
    };

    const int m0w = (wid & 3) * 32;
    const int n0w = (wid >> 2) * 64;
    uint32_t aRow[2], aXor[2];
    const uint32_t aCol = (uint32_t)((lane >> 4) << 4);
    #pragma unroll
    for (int mf = 0; mf < 2; mf++) {
        int r = m0w + mf * 16 + (lane & 15);
        aRow[mf] = (uint32_t)(r * 64);
        aXor[mf] = (uint32_t)(((r >> 1) & 3) << 4);
    }
    uint32_t bRow[4], bXor[4];
    const uint32_t bCol = (uint32_t)(((lane >> 3) & 1) << 4);
    #pragma unroll
    for (int nb = 0; nb < 4; nb++) {
        int nrow = n0w + nb * 16 + ((lane >> 4) << 3) + (lane & 7);
        bRow[nb] = (uint32_t)(nrow * 64);
        bXor[nb] = (uint32_t)(((nrow >> 1) & 3) << 4);
    }

    float acc[2][8][4];
    #pragma unroll
    for (int mf = 0; mf < 2; mf++)
        #pragma unroll
        for (int nf = 0; nf < 8; nf++)
            #pragma unroll
            for (int u = 0; u < 4; u++) acc[mf][nf][u] = 0.f;

    load_stage(0);
    load_stage(1);

    for (int s = 0; s < NSTG; s++) {
        if (s < NSTG - 1) cp_wait<1>(); else cp_wait<0>();
        __syncthreads();
        if (s + 2 < NSTG) load_stage(s + 2);   // overlaps this stage's compute
        uint32_t base = sb + (uint32_t)(s % 3) * STG_B;
        #pragma unroll
        for (int k16 = 0; k16 < 2; k16++) {
            uint32_t kb = (uint32_t)(k16 * 32);
            uint32_t ah[2][4], al[2][4], bh[4][4], bl[4][4];
            #pragma unroll
            for (int mf = 0; mf < 2; mf++) {
                uint32_t off = aRow[mf] + ((aCol | kb) ^ aXor[mf]);
                ldsm4(ah[mf], base + off);
                ldsm4(al[mf], base + MAT_B + off);
            }
            #pragma unroll
            for (int nb = 0; nb < 4; nb++) {
                uint32_t off = bRow[nb] + ((bCol | kb) ^ bXor[nb]);
                ldsm4(bh[nb], base + 2 * MAT_B + off);
                ldsm4(bl[nb], base + 3 * MAT_B + off);
            }
            #pragma unroll
            for (int mf = 0; mf < 2; mf++)
                #pragma unroll
                for (int nb = 0; nb < 4; nb++)
                    #pragma unroll
                    for (int hf = 0; hf < 2; hf++) {
                        int nf = nb * 2 + hf;
                        mma16816(acc[mf][nf], ah[mf], &bh[nb][hf * 2]);
                        mma16816(acc[mf][nf], ah[mf], &bl[nb][hf * 2]);
                        mma16816(acc[mf][nf], al[mf], &bh[nb][hf * 2]);
                    }
        }
        // 3-stage ring: no trailing barrier needed
    }

    // ---- epilogue: write f32 results
    size_t colbase = (size_t)nt * 128;
    #pragma unroll
    for (int mf = 0; mf < 2; mf++) {
        int r0 = mt * 128 + m0w + mf * 16 + (lane >> 2);
        #pragma unroll
        for (int nf = 0; nf < 8; nf++) {
            int cb2 = n0w + nf * 8 + (lane & 3) * 2;
            float* d0 = g_qkv + (size_t)r0 * NCOL + colbase + cb2;
            float* d1 = g_qkv + (size_t)(r0 + 8) * NCOL + colbase + cb2;
            *(float2*)d0 = make_float2(acc[mf][nf][0], acc[mf][nf][1]);
            *(float2*)d1 = make_float2(acc[mf][nf][2], acc[mf][nf][3]);
        }
    }

    // ---- fused per-row partial BN stats over this CTA's 128 cols
    float prs[4] = {0, 0, 0, 0}, prq[4] = {0, 0, 0, 0};
    #pragma unroll
    for (int mf = 0; mf < 2; mf++)
        #pragma unroll
        for (int nf = 0; nf < 8; nf++) {
            prs[mf * 2 + 0] += acc[mf][nf][0] + acc[mf][nf][1];
            prq[mf * 2 + 0] += acc[mf][nf][0] * acc[mf][nf][0] + acc[mf][nf][1] * acc[mf][nf][1];
            prs[mf * 2 + 1] += acc[mf][nf][2] + acc[mf][nf][3];
            prq[mf * 2 + 1] += acc[mf][nf][2] * acc[mf][nf][2] + acc[mf][nf][3] * acc[mf][nf][3];
        }
    #pragma unroll
    for (int off = 1; off <= 2; off <<= 1)
        #pragma unroll
        for (int u = 0; u < 4; u++) {
            prs[u] += __shfl_xor_sync(0xffffffffu, prs[u], off);
            prq[u] += __shfl_xor_sync(0xffffffffu, prq[u], off);
        }
    __syncthreads();
    float2* sred = (float2*)smem;       // [8 warps][32 rows]
    if ((lane & 3) == 0) {
        int q = lane >> 2;
        #pragma unroll
        for (int mf = 0; mf < 2; mf++)
            #pragma unroll
            for (int h = 0; h < 2; h++) {
                int rl = mf * 16 + h * 8 + q;
                sred[wid * 32 + rl] = make_float2(prs[mf * 2 + h], prq[mf * 2 + h]);
            }
    }
    __syncthreads();
    if (tid < 128) {
        int mg = tid >> 5, rl = tid & 31;
        float2 a2 = sred[mg * 32 + rl];
        float2 b2 = sred[(mg + 4) * 32 + rl];
        g_qpart[(size_t)(mt * 128 + mg * 32 + rl) * NTILE + nt] =
            make_float2(a2.x + b2.x, a2.y + b2.y);
    }
}

// ---------------- K2: reduce qkv partials -> BN coefficients ----------------
__global__ void k_qred(const float* __restrict__ gq, const float* __restrict__ bq) {
    int o = blockIdx.x;
    __shared__ double rs[128], rq2[128];
    double s = 0.0, q = 0.0;
    for (int p = threadIdx.x; p < NTILE; p += 128) {
        float2 v = g_qpart[(size_t)o * NTILE + p];
        s += (double)v.x; q += (double)v.y;
    }
    rs[threadIdx.x] = s; rq2[threadIdx.x] = q;
    __syncthreads();
    for (int st = 64; st > 0; st >>= 1) {
        if (threadIdx.x < st) { rs[threadIdx.x] += rs[threadIdx.x + st]; rq2[threadIdx.x] += rq2[threadIdx.x + st]; }
        __syncthreads();
    }
    if (threadIdx.x == 0) {
        double mean = rs[0] / (double)NCOL;
        double var  = rq2[0] / (double)NCOL - mean * mean;
        float a = gq[o] * (float)(1.0 / sqrt(var + 1e-5));
        g_qkvA[o] = a;
        g_qkvB[o] = bq[o] - (float)mean * a;
    }
}

// ---------------- K3: qk / qr / kr per (b,g) block, 4x4 register tiles ----------------
__global__ __launch_bounds__(224) void k_sim(const float* __restrict__ rel) {
    int blk = blockIdx.x;
    int b = blk >> 3, g = blk & 7;
    int n = b / 56, w = b - n * 56;
    long colbase = (long)n * HW2 + w * 56;

    __shared__ float q_s[32][60];
    __shared__ float k_s[32][60];
    __shared__ float rqs[32][112];
    __shared__ float rks[32][112];
    __shared__ float wred[7][6];

    int tid = threadIdx.x;
    for (int idx = tid; idx < 64 * 56; idx += 224) {
        int c = idx / 56, i = idx - c * 56;
        int o = g * 128 + c;
        float v = g_qkv[(long)o * NCOL + colbase + i] * g_qkvA[o] + g_qkvB[o];
        if (c < 32) q_s[c][i] = v; else k_s[c - 32][i] = v;
    }
    for (int idx = tid; idx < 64 * 111; idx += 224) {
        int c = idx / 111, t2 = idx - c * 111;
        float v = rel[c * 111 + t2];
        if (c < 32) rqs[c][t2] = v; else rks[c - 32][t2] = v;
    }
    if (tid < 64) { if (tid < 32) rqs[tid][111] = 0.f; else rks[tid - 32][111] = 0.f; }
    __syncthreads();

    float qk_a[4][4], qr_a[4][4], kr_a[4][4];
    #pragma unroll
    for (int a = 0; a < 4; a++)
        #pragma unroll
        for (int b2 = 0; b2 < 4; b2++) { qk_a[a][b2] = 0.f; qr_a[a][b2] = 0.f; kr_a[a][b2] = 0.f; }

    float s0 = 0, s1 = 0, s2 = 0, q0 = 0, q1 = 0, q2 = 0;

    if (tid < 196) {
        const int it = tid / 14, jt = tid % 14;
        const int i0 = it * 4, jj0 = jt * 4;
        const int dq = i0 - jj0 + 52;
        const int dk = jj0 - i0 + 52;

        #pragma unroll 4
        for (int c = 0; c < 32; c++) {
            const float4 qv = *(const float4*)&q_s[c][i0];
            const float4 kv = *(const float4*)&k_s[c][jj0];
            const float4 r0 = *(const float4*)&rqs[c][dq];
            const float4 r1 = *(const float4*)&rqs[c][dq + 4];
            const float4 t0 = *(const float4*)&rks[c][dk];
            const float4 t1 = *(const float4*)&rks[c][dk + 4];
            const float qa[4] = {qv.x, qv.y, qv.z, qv.w};
            const float kb[4] = {kv.x, kv.y, kv.z, kv.w};
            const float rqe[7] = {r0.x, r0.y, r0.z, r0.w, r1.x, r1.y, r1.z};
            const float rke[7] = {t0.x, t0.y, t0.z, t0.w, t1.x, t1.y, t1.z};
            #pragma unroll
            for (int a = 0; a < 4; a++)
                #pragma unroll
                for (int b2 = 0; b2 < 4; b2++) {
                    qk_a[a][b2] += qa[a] * kb[b2];
                    qr_a[a][b2] += qa[a] * rqe[a - b2 + 3];
                    kr_a[a][b2] += kb[b2] * rke[b2 - a + 3];
                }
        }

        float* oqk = g_qk + (long)blk * HW2;
        float* oqr = g_qr + (long)blk * HW2;
        float* okr = g_kr + (long)blk * HW2;
        #pragma unroll
        for (int a = 0; a < 4; a++) {
            int i = i0 + a;
            *(float4*)&oqk[i * 56 + jj0] = make_float4(qk_a[a][0], qk_a[a][1], qk_a[a][2], qk_a[a][3]);
            *(float4*)&oqr[i * 56 + jj0] = make_float4(qr_a[a][0], qr_a[a][1], qr_a[a][2], qr_a[a][3]);
            *(float4*)&okr[i * 56 + jj0] = make_float4(kr_a[a][0], kr_a[a][1], kr_a[a][2], kr_a[a][3]);
            #pragma unroll
            for (int b2 = 0; b2 < 4; b2++) {
                float v0 = qk_a[a][b2], v1 = qr_a[a][b2], v2 = kr_a[a][b2];
                s0 += v0; q0 += v0 * v0;
                s1 += v1; q1 += v1 * v1;
                s2 += v2; q2 += v2 * v2;
            }
        }
    }

    #pragma unroll
    for (int off = 16; off > 0; off >>= 1) {
        s0 += __shfl_down_sync(0xffffffffu, s0, off);
        s1 += __shfl_down_sync(0xffffffffu, s1, off);
        s2 += __shfl_down_sync(0xffffffffu, s2, off);
        q0 += __shfl_down_sync(0xffffffffu, q0, off);
        q1 += __shfl_down_sync(0xffffffffu, q1, off);
        q2 += __shfl_down_sync(0xffffffffu, q2, off);
    }
    int lane = tid & 31, warp = tid >> 5;
    if (lane == 0) {
        wred[warp][0] = s0; wred[warp][1] = s1; wred[warp][2] = s2;
        wred[warp][3] = q0; wred[warp][4] = q1; wred[warp][5] = q2;
    }
    __syncthreads();
    if (tid == 0) {
        float t[6] = {0, 0, 0, 0, 0, 0};
        for (int wv = 0; wv < 7; wv++)
            for (int u = 0; u < 6; u++) t[u] += wred[wv][u];
        for (int u = 0; u < 6; u++)
            g_bstat[(u * NGRP + g) * 896 + b] = t[u];
    }
}

// ---------------- K4: reduce sim stat partials ----------------
__global__ void k_simred() {
    int qg = blockIdx.x;                   // 0..47
    __shared__ double rd[128];
    double acc = 0.0;
    for (int b = threadIdx.x; b < 896; b += 128)
        acc += (double)g_bstat[qg * 896 + b];
    rd[threadIdx.x] = acc;
    __syncthreads();
    for (int st = 64; st > 0; st >>= 1) {
        if (threadIdx.x < st) rd[threadIdx.x] += rd[threadIdx.x + st];
        __syncthreads();
    }
    if (threadIdx.x == 0) g_sred[qg] = rd[0];
}

// ---------------- K5: sim BN coefficients ----------------
__global__ void k_simcoef(const float* __restrict__ gs, const float* __restrict__ bs) {
    int g = threadIdx.x;
    if (g >= NGRP) return;
    const double ntot = 896.0 * 3136.0;
    float cc = 0.f;
    for (int t = 0; t < 3; t++) {
        double S = g_sred[t * 8 + g];
        double Q = g_sred[(t + 3) * 8 + g];
        double mean = S / ntot;
        double var  = Q / ntot - mean * mean;
        float a = gs[t * 8 + g] * (float)(1.0 / sqrt(var + 1e-5));
        g_simA[t * 8 + g] = a;
        cc += bs[t * 8 + g] - (float)mean * a;
    }
    g_simC[g] = cc;
}

// ---------------- K6: softmax + sv/sve per (b,g) + fused out-BN partials ----------------
// Pair-remap: c = tid>>1, jh = tid&1 (adjacent lanes) -> shfl_xor(1) reduction,
// no red[] smem (48->43 KB, 5 CTAs/SM). Inner loop identical to R16.
__global__ __launch_bounds__(128) void k_attn(const float* __restrict__ rel) {
    int blk = blockIdx.x;
    int b = blk >> 3, g = blk & 7;
    int n = b / 56, w = b - n * 56;
    long colbase = (long)n * HW2 + w * 56;

    __shared__ float v_s[64][57];
    __shared__ float rv[64][111];
    __shared__ float p_s[4][56];

    int tid = threadIdx.x;
    for (int idx = tid; idx < 64 * 56; idx += 128) {
        int c = idx / 56, i = idx - c * 56;
        int o = g * 128 + 64 + c;
        v_s[c][i] = g_qkv[(long)o * NCOL + colbase + i] * g_qkvA[o] + g_qkvB[o];
    }
    for (int idx = tid; idx < 64 * 111; idx += 128) {
        int c = idx / 111, t2 = idx - c * 111;
        rv[c][t2] = rel[(64 + c) * 111 + t2];
    }
    float a0 = g_simA[g], a1 = g_simA[8 + g], a2 = g_simA[16 + g], cc = g_simC[g];
    const float* bqk = g_qk + (long)blk * HW2;
    const float* bqr = g_qr + (long)blk * HW2;
    const float* bkr = g_kr + (long)blk * HW2;
    __syncthreads();

    int lane = tid & 31, warp = tid >> 5;
    const int c = tid >> 1, jh = tid & 1;  // pair-adjacent mapping
    const int jbeg = jh * 28;

    float ssv = 0.f, qsv = 0.f, sse = 0.f, qse = 0.f;   // fused out-BN partials

    for (int iq = 0; iq < 14; iq++) {
        int i0 = iq * 4;
        {
            int i = i0 + warp;
            int j1 = lane, j2 = lane + 32;
            const float* pk = bqk + i * 56;
            const float* pr = bqr + i * 56;
            const float* pl = bkr + i * 56;
            float sA = a0 * pk[j1] + a1 * pr[j1] + a2 * pl[j1] + cc;
            float sB = (j2 < 56) ? (a0 * pk[j2] + a1 * pr[j2] + a2 * pl[j2] + cc) : -1e30f;
            float m = fmaxf(sA, sB);
            #pragma unroll
            for (int off = 16; off > 0; off >>= 1)
                m = fmaxf(m, __shfl_xor_sync(0xffffffffu, m, off));
            float e1 = __expf(sA - m);
            float e2 = (j2 < 56) ? __expf(sB - m) : 0.f;
            float sm = e1 + e2;
            #pragma unroll
            for (int off = 16; off > 0; off >>= 1)
                sm += __shfl_xor_sync(0xffffffffu, sm, off);
            float inv = 1.f / sm;
            p_s[warp][j1] = e1 * inv;
            if (j2 < 56) p_s[warp][j2] = e2 * inv;
        }
        __syncthreads();

        // ---- phase B: identical inner loop to R16 ----
        float sv[4] = {0, 0, 0, 0}, se[4] = {0, 0, 0, 0};
        float win[4];
        #pragma unroll
        for (int d = 0; d < 4; d++) win[d] = rv[c][i0 + d - jbeg + 55];
        for (int jo = 0; jo < 28; jo++) {
            int j = jbeg + jo;
            float vv = v_s[c][j];
            #pragma unroll
            for (int d = 0; d < 4; d++) {
                float p = p_s[d][j];
                sv[d] += p * vv;
                se[d] += p * win[d];
            }
            if (jo < 27) {
                #pragma unroll
                for (int d = 3; d > 0; d--) win[d] = win[d - 1];
                win[0] = rv[c][i0 - j + 54];
            }
        }

        // ---- pair reduction via shfl (partner = lane^1, same warp) ----
        #pragma unroll
        for (int d = 0; d < 4; d++) {
            float svt = sv[d] + __shfl_xor_sync(0xffffffffu, sv[d], 1);
            float set = se[d] + __shfl_xor_sync(0xffffffffu, se[d], 1);
            if (jh == 0) {
                long row = (long)b * 56 + (i0 + d);
                ((float2*)(g_ov + row * O2 + g * 128))[c] = make_float2(svt, set);
                ssv += svt; qsv += svt * svt;
                sse += set; qse += set * set;
            }
        }
        __syncthreads();   // protect p_s against next iteration's softmax writes
    }

    if (jh == 0) {
        int o0 = g * 128 + 2 * c;
        g_opart2[(size_t)o0 * 896 + b]       = make_float2(ssv, qsv);
        g_opart2[(size_t)(o0 + 1) * 896 + b] = make_float2(sse, qse);
    }
}

// ---------------- K7: reduce out-BN partials -> coefficients ----------------
__global__ void k_ofin2(const float* __restrict__ go, const float* __restrict__ bo) {
    int o = blockIdx.x;
    __shared__ double rs[128], rq2[128];
    double s = 0.0, q = 0.0;
    for (int p = threadIdx.x; p < 896; p += 128) {
        float2 v = g_opart2[(size_t)o * 896 + p];
        s += (double)v.x; q += (double)v.y;
    }
    rs[threadIdx.x] = s; rq2[threadIdx.x] = q;
    __syncthreads();
    for (int st = 64; st > 0; st >>= 1) {
        if (threadIdx.x < st) { rs[threadIdx.x] += rs[threadIdx.x + st]; rq2[threadIdx.x] += rq2[threadIdx.x + st]; }
        __syncthreads();
    }
    if (threadIdx.x == 0) {
        double mean = rs[0] / (double)NCOL;
        double var  = rq2[0] / (double)NCOL - mean * mean;
        float a = go[o] * (float)(1.0 / sqrt(var + 1e-5));
        g_oA[o] = a;
        g_oB[o] = bo[o] - (float)mean * a;
    }
}

// ---------------- K8: final BN + pair-sum + transpose ----------------
__global__ __launch_bounds__(256) void k_out(float* __restrict__ out) {
    int pt = blockIdx.x, h = blockIdx.y, n = blockIdx.z;
    int p0 = pt * 64;
    __shared__ float tile[56][65];
    int tid = threadIdx.x;
    for (int lin = tid; lin < 56 * 64; lin += 256) {
        int w = lin >> 6, pl = lin & 63;
        int p = p0 + pl;
        long row = (long)n * HW2 + w * 56 + h;
        float2 v = *(const float2*)&g_ov[row * O2 + p * 2];
        tile[w][pl] = g_oA[2 * p] * v.x + g_oA[2 * p + 1] * v.y + g_oB[2 * p] + g_oB[2 * p + 1];
    }
    __syncthreads();
    for (int lin = tid; lin < 56 * 64; lin += 256) {
        int pl = lin / 56, w2 = lin - pl * 56;
        out[(((long)n * 512 + p0 + pl) * 56 + h) * 56 + w2] = tile[w2][pl];
    }
}

// ---------------- launch ----------------
extern "C" void kernel_launch(void* const* d_in, const int* in_sizes, int n_in,
                              void* d_out, int out_size) {
    const float* x     = (const float*)d_in[0];
    const float* w_qkv = (const float*)d_in[1];
    const float* rel   = (const float*)d_in[2];
    const float* g_q   = (const float*)d_in[3];
    const float* b_q   = (const float*)d_in[4];
    const float* g_s   = (const float*)d_in[5];
    const float* b_s   = (const float*)d_in[6];
    const float* g_o   = (const float*)d_in[7];
    const float* b_o   = (const float*)d_in[8];
    float* out = (float*)d_out;

    cudaFuncSetAttribute(k_gemm_mma, cudaFuncAttributeMaxDynamicSharedMemorySize, GEMM_SMEM);

    k_wsplit<<<O2 * CIN / 1024, 256>>>(w_qkv);
    k_split_x<<<dim3(32, 7, NB), 256>>>(x);
    k_gemm_mma<<<dim3(8, NTILE), 256, GEMM_SMEM>>>();
    k_qred<<<O2, 128>>>(g_q, b_q);
    k_sim<<<NBLK_BG, 224>>>(rel);
    k_simred<<<48, 128>>>();
    k_simcoef<<<1, 32>>>(g_s, b_s);
    k_attn<<<NBLK_BG, 128>>>(rel);
    k_ofin2<<<O2, 128>>>(g_o, b_o);
    k_out<<<dim3(8, 56, NB), 256>>>(out);
}